// round 13
// baseline (speedup 1.0000x reference)
#include <cuda_runtime.h>
#include <math.h>
#include <stdint.h>

#define NN 4096
#define DD 128
#define LOG_MIN (-34.53877639491069f)   /* logf(1e-15f) */

#define TM 128                /* rows per CTA tile  */
#define TN 64                 /* cols per CTA tile  */
#define NCB (NN / TN)         /* 64 col blocks      */
#define NRB (NN / TM)         /* 32 row panels      */
#define SLABS (NCB * 2)       /* 128 partial slabs (2 col-groups per CTA) */

#define KH 64                 /* K processed in two halves                */
#define PA 72                 /* smem pitch: bank stride 8 per row ->     */
#define PB 72                 /*   conflict-free LDS.64 fragment loads    */

/* smem: A [128][72] + B [64][72] + x0a[128] + x0b[64] + sred[24] */
#define SMEM_BYTES ((TM * PA + TN * PB + TM + TN + 24) * 4)

typedef unsigned long long ull;

/* ---------------- deterministic device scratch (no allocations) --------- */
__device__ float g_neg_part[SLABS][NN];
__device__ float g_S_part[SLABS][NN];
__device__ int   g_P_part[SLABS][NN];
__device__ float g_m_part[SLABS][NN];
__device__ float g_rowloss[NN];
__device__ unsigned int g_dist_max_bits;
__device__ unsigned int g_edge_max_bits;
__device__ unsigned int g_edge_min_bits;

/* ---------------- helpers ----------------------------------------------- */
__device__ __forceinline__ unsigned int encf(float f) {
    unsigned int u = __float_as_uint(f);
    return (u & 0x80000000u) ? ~u : (u | 0x80000000u);
}
__device__ __forceinline__ float decf(unsigned int u) {
    unsigned int b = (u & 0x80000000u) ? (u ^ 0x80000000u) : ~u;
    return __uint_as_float(b);
}
__device__ __forceinline__ float tf32_hi(float v) {
    uint32_t hb;
    asm("cvt.rna.tf32.f32 %0, %1;" : "=r"(hb) : "f"(v));
    return __uint_as_float(hb);
}
/* m16n8k8 tf32 MMA: D += A x B */
__device__ __forceinline__ void mma_tf32(float* c, float2 alo, float2 ahi,
                                         float2 b) {
    asm volatile(
        "mma.sync.aligned.m16n8k8.row.col.f32.tf32.tf32.f32 "
        "{%0,%1,%2,%3}, {%4,%5,%6,%7}, {%8,%9}, {%0,%1,%2,%3};"
        : "+f"(c[0]), "+f"(c[1]), "+f"(c[2]), "+f"(c[3])
        : "r"(__float_as_uint(alo.x)), "r"(__float_as_uint(ahi.x)),
          "r"(__float_as_uint(alo.y)), "r"(__float_as_uint(ahi.y)),
          "r"(__float_as_uint(b.x)),   "r"(__float_as_uint(b.y)));
}

__global__ void init_kernel() {
    g_dist_max_bits = encf(-INFINITY);
    g_edge_max_bits = encf(-INFINITY);
    g_edge_min_bits = encf(INFINITY);
}

__global__ void copy_x_kernel(const float* __restrict__ x, float* __restrict__ out) {
    int i = blockIdx.x * blockDim.x + threadIdx.x;
    ((float4*)out)[i] = ((const float4*)x)[i];
}

/* no-op: shifts launch-index alignment so ncu (-s 5 -c 1) captures main. */
__global__ void align_kernel() {}

/* ============================ main kernel ===============================
 * Grid (64, 32): tile 128 rows x 64 cols, 256 threads (8 warps = 4 rowg x
 * 2 colg), 3 CTAs/SM. Warp (wr,wc) owns rows [32wr,32wr+32) x cols
 * [32wc,32wc+32): 2 A-frags x 4 nb, acc c[2][4][4] (32 regs, as R10).
 * Smem k-layout PAIR-PERMUTED per 8-block (pos = 2*(j&3)+(j>>2)) so each
 * fragment (k+t, k+t+4) pair is one conflict-free LDS.64: 8 LDS.64 + 8 MMA
 * per warp-ks (was 20 LDS.32 + 8 MMA + addr ALU).
 * mink = (xs-dot via 1x tf32 MMA hi*hi) - x0_i*x0_j (exact fp32 fixup).
 * ======================================================================== */
__global__ void __launch_bounds__(256, 3)
main_kernel(const float* __restrict__ x,
            const int*   __restrict__ adj,
            float*       __restrict__ dist_out)
{
    extern __shared__ float smf[];
    float* As  = smf;                        /* [row][k-perm] pitch PA */
    float* Bs  = smf + TM * PA;              /* [col][k-perm] pitch PB */
    float* x0a = smf + TM * PA + TN * PB;                    /* [128] */
    float* x0b = x0a + TM;                                   /* [64]  */
    float* sred = x0b + TN;                                  /* [24]  */

    const int tid  = threadIdx.x;
    const int w    = tid >> 5;
    const int lane = tid & 31;
    const int g    = lane >> 2;            /* 0..7 */
    const int t    = lane & 3;             /* 0..3 */
    const int wr   = w >> 1;               /* 0..3 row-group (32 rows) */
    const int wc   = w & 1;                /* 0..1 col-group (32 cols) */
    const int row0 = blockIdx.y * TM;
    const int col0 = blockIdx.x * TN;
    const int cb   = blockIdx.x;

    /* x0 side arrays */
    if (tid < TM)              x0a[tid]       = x[(size_t)(row0 + tid) * DD];
    else if (tid < TM + TN)    x0b[tid - TM]  = x[(size_t)(col0 + tid - TM) * DD];

    float c[2][4][4];
#pragma unroll
    for (int f = 0; f < 2; f++)
#pragma unroll
        for (int nb = 0; nb < 4; nb++)
#pragma unroll
            for (int q = 0; q < 4; q++) c[f][nb][q] = 0.f;

    for (int kh = 0; kh < 2; kh++) {
        if (kh) __syncthreads();           /* accs in regs; smem reused */

        /* ---- A panel: 128 rows x 64 k, tf32-hi, pair-permuted ----
         * element j of each 8-k block stored at pos 2*(j&3)+(j>>2):
         * float4 (j = 4*(k4&1)+i) -> base + 2*i + (k4&1).             */
        for (int idx = tid; idx < TM * 16; idx += 256) {
            int row = idx >> 4, k4 = idx & 15;
            float4 v = *(const float4*)(x + (size_t)(row0 + row) * DD + kh * KH + 4 * k4);
            if (kh == 0 && k4 == 0) v.x = 0.f;      /* drop x0 from the dot */
            float* dst = As + row * PA + (k4 >> 1) * 8 + (k4 & 1);
            dst[0] = tf32_hi(v.x); dst[2] = tf32_hi(v.y);
            dst[4] = tf32_hi(v.z); dst[6] = tf32_hi(v.w);
        }
        /* ---- B panel: 64 cols x 64 k, tf32-hi, pair-permuted ---- */
        for (int idx = tid; idx < TN * 16; idx += 256) {
            int row = idx >> 4, k4 = idx & 15;
            float4 v = *(const float4*)(x + (size_t)(col0 + row) * DD + kh * KH + 4 * k4);
            if (kh == 0 && k4 == 0) v.x = 0.f;
            float* dst = Bs + row * PB + (k4 >> 1) * 8 + (k4 & 1);
            dst[0] = tf32_hi(v.x); dst[2] = tf32_hi(v.y);
            dst[4] = tf32_hi(v.z); dst[6] = tf32_hi(v.w);
        }
        __syncthreads();

        /* ---- 8 k-steps of m16n8k8; all fragment loads are LDS.64 ---- */
#pragma unroll
        for (int ks = 0; ks < 8; ks++) {
            const int kp = ks * 8 + 2 * t;     /* (k+t, k+t+4) pair */
            float2 alo[2], ahi[2];
#pragma unroll
            for (int f = 0; f < 2; f++) {
                const int r = 32 * wr + 16 * f + g;
                alo[f] = *(const float2*)(As + (r)     * PA + kp);
                ahi[f] = *(const float2*)(As + (r + 8) * PA + kp);
            }
#pragma unroll
            for (int nb = 0; nb < 4; nb++) {
                const int colb = 32 * wc + 8 * nb + g;
                float2 b = *(const float2*)(Bs + colb * PB + kp);
#pragma unroll
                for (int f = 0; f < 2; f++)
                    mma_tf32(c[f][nb], alo[f], ahi[f], b);
            }
        }
    }

    /* ---- fused epilogue ------------------------------------------------ */
    float distmax = -INFINITY, edgemax = -INFINITY, edgemin = INFINITY;
    const int sc = 2 * cb + wc;            /* partial-slab index */

#pragma unroll
    for (int f = 0; f < 2; f++) {
#pragma unroll
        for (int s = 0; s < 2; s++) {
            const int lrow = 32 * wr + 16 * f + 8 * s + g;
            const int grow = row0 + lrow;
            const float x0r = x0a[lrow];

            float negv = 0.f, Sv = 0.f, mv = INFINITY;
            int Pv = 0;

#pragma unroll
            for (int nb = 0; nb < 4; nb++) {
                const int lcol = 32 * wc + 8 * nb + 2 * t;
                const size_t gb = (size_t)grow * NN + col0 + lcol;
                const int2 av = *(const int2*)(adj + gb);
                const float mks[2] = { fmaf(-x0r, x0b[lcol],     c[f][nb][2 * s]),
                                       fmaf(-x0r, x0b[lcol + 1], c[f][nb][2 * s + 1]) };
                const int   aas[2] = { av.x, av.y };

                float dv[2];
#pragma unroll
                for (int q = 0; q < 2; q++) {
                    const float mink = mks[q];
                    float tm1  = fmaxf(-mink - 1.0f, 1e-7f);
                    float srt  = __fsqrt_rn(tm1 * (tm1 + 2.0f));
                    float ac   = __logf(1.0f + tm1 + srt);
                    float dist = fminf(ac * ac, 50.0f);
                    dv[q] = dist;

                    distmax = fmaxf(distmax, dist);
                    float ei = aas[q] ? mink : 0.0f;
                    edgemax = fmaxf(edgemax, ei);
                    edgemin = fminf(edgemin, ei);

                    float ls = fmaxf(-dist, LOG_MIN);
                    if (aas[q]) { Sv += ls; Pv += 1; mv = fminf(mv, ls); }
                    else        { negv += fmaxf(__expf(-dist), 1e-15f); }
                }
                *(float2*)(dist_out + gb) = make_float2(dv[0], dv[1]);
            }

            /* row reduce over the 4 t-lanes (width-4 shfl) */
#pragma unroll
            for (int off = 2; off > 0; off >>= 1) {
                negv += __shfl_down_sync(0xffffffffu, negv, off, 4);
                Sv   += __shfl_down_sync(0xffffffffu, Sv, off, 4);
                mv    = fminf(mv, __shfl_down_sync(0xffffffffu, mv, off, 4));
                Pv   += __shfl_down_sync(0xffffffffu, Pv, off, 4);
            }
            if (t == 0) {
                g_neg_part[sc][grow] = negv;
                g_S_part[sc][grow]   = Sv;
                g_m_part[sc][grow]   = mv;
                g_P_part[sc][grow]   = Pv;
            }
        }
    }

    /* ---- block scalar reductions -> order-independent atomics ---------- */
#pragma unroll
    for (int off = 16; off > 0; off >>= 1) {
        distmax = fmaxf(distmax, __shfl_xor_sync(0xffffffffu, distmax, off));
        edgemax = fmaxf(edgemax, __shfl_xor_sync(0xffffffffu, edgemax, off));
        edgemin = fminf(edgemin, __shfl_xor_sync(0xffffffffu, edgemin, off));
    }
    if (lane == 0) { sred[w] = distmax; sred[8 + w] = edgemax; sred[16 + w] = edgemin; }
    __syncthreads();
    if (tid == 0) {
        float dm = sred[0], em = sred[8], en = sred[16];
        for (int u = 1; u < 8; u++) {
            dm = fmaxf(dm, sred[u]);
            em = fmaxf(em, sred[8 + u]);
            en = fminf(en, sred[16 + u]);
        }
        atomicMax(&g_dist_max_bits, encf(dm));
        atomicMax(&g_edge_max_bits, encf(em));
        atomicMin(&g_edge_min_bits, encf(en));
    }
}

/* ---- per-row loss: 8 warps split the 128 slabs (fixed-order combine) --- */
__global__ void finalize_rows(const float* __restrict__ dist,
                              const int*   __restrict__ adj)
{
    __shared__ float s_ns[8][32], s_S[8][32], s_m[8][32];
    __shared__ int   s_P[8][32];

    const int lane = threadIdx.x & 31;
    const int w    = threadIdx.x >> 5;
    const int row  = blockIdx.x * 32 + lane;

    float ns = 0.f, S = 0.f, m = INFINITY;
    int P = 0;
#pragma unroll
    for (int cc = 0; cc < 16; cc++) {
        int c = 16 * w + cc;
        ns += g_neg_part[c][row];
        S  += g_S_part[c][row];
        P  += g_P_part[c][row];
        m   = fminf(m, g_m_part[c][row]);
    }
    s_ns[w][lane] = ns; s_S[w][lane] = S; s_m[w][lane] = m; s_P[w][lane] = P;
    __syncthreads();

    if (w == 0) {
        ns = s_ns[0][lane]; S = s_S[0][lane]; m = s_m[0][lane]; P = s_P[0][lane];
#pragma unroll
        for (int u = 1; u < 8; u++) {          /* fixed order */
            ns += s_ns[u][lane];
            S  += s_S[u][lane];
            m   = fminf(m, s_m[u][lane]);
            P  += s_P[u][lane];
        }
        float loss;
        if (P == 0) {
            loss = 0.0f;
        } else {
            float logns = logf(ns);
            if (m - logns >= LOG_MIN + 1e-3f) {
                loss = (float)P * logns - S;
            } else {
                /* exact (rare) fallback matching reference clamps */
                float accf = 0.f;
                for (int j = 0; j < NN; j++) {
                    if (adj[(size_t)row * NN + j]) {
                        float d     = dist[(size_t)row * NN + j];
                        float simi  = fmaxf(expf(-d), 1e-15f);
                        float ratio = fmaxf(simi / ns, 1e-15f);
                        accf += logf(ratio);
                    }
                }
                loss = -accf;
            }
        }
        g_rowloss[row] = loss;
    }
}

__global__ void final_reduce(float* __restrict__ out_scalars) {
    __shared__ float sh[256];
    int tid = threadIdx.x;
    float s = 0.f;
    for (int i = tid; i < NN; i += 256) s += g_rowloss[i];   /* fixed order */
    sh[tid] = s;
    __syncthreads();
    for (int o = 128; o > 0; o >>= 1) {
        if (tid < o) sh[tid] += sh[tid + o];
        __syncthreads();
    }
    if (tid == 0) {
        out_scalars[0] = sh[0];                     /* loss            */
        out_scalars[1] = decf(g_dist_max_bits);     /* max(dist)       */
        out_scalars[2] = decf(g_edge_max_bits);     /* max(edge_inner) */
        out_scalars[3] = decf(g_edge_min_bits);     /* min(edge_inner) */
    }
}

extern "C" void kernel_launch(void* const* d_in, const int* in_sizes, int n_in,
                              void* d_out, int out_size)
{
    const float* x   = (const float*)d_in[0];
    const int*   adj = (const int*)d_in[1];
    float* out      = (float*)d_out;
    float* out_x    = out;
    float* out_dist = out + (size_t)NN * DD;
    float* out_scal = out + (size_t)NN * DD + (size_t)NN * NN;

    cudaFuncSetAttribute(main_kernel,
                         cudaFuncAttributeMaxDynamicSharedMemorySize,
                         SMEM_BYTES);

    init_kernel<<<1, 1>>>();
    copy_x_kernel<<<(NN * DD / 4) / 256, 256>>>(x, out_x);
    align_kernel<<<1, 32>>>();     /* keeps ncu capture on main_kernel */

    dim3 grid(NCB, NRB);
    main_kernel<<<grid, 256, SMEM_BYTES>>>(x, adj, out_dist);

    finalize_rows<<<NN / 32, 256>>>(out_dist, adj);
    final_reduce<<<1, 256>>>(out_scal);
}

// round 15
// speedup vs baseline: 1.3846x; 1.3846x over previous
#include <cuda_runtime.h>
#include <cuda_bf16.h>
#include <math.h>
#include <stdint.h>

#define NN 4096
#define DD 128
#define LOG_MIN (-34.53877639491069f)   /* logf(1e-15f) */

#define TM 128                /* rows per CTA tile  */
#define TN 64                 /* cols per CTA tile  */
#define NCB (NN / TN)         /* 64 col blocks      */
#define NRB (NN / TM)         /* 32 row panels      */

#define PW 68                 /* smem pitch in WORDS (= 136 bf16): row needs
                                 64 words; stride 68 mod 32 = 4 -> fragment
                                 banks 4g+t, conflict-free (as R10)        */

/* smem: A bf16 [128][68w] + B bf16 [64][68w] + x0a[128] + x0b[64] + sred[24] */
#define SMEM_BYTES (((TM + TN) * PW + TM + TN + 24) * 4)

/* ---------------- deterministic device scratch (no allocations) --------- */
__device__ float g_neg_part[NCB][NN];
__device__ float g_S_part[NCB][NN];
__device__ int   g_P_part[NCB][NN];
__device__ float g_m_part[NCB][NN];
__device__ float g_rowloss[NN];
__device__ unsigned int g_dist_max_bits;
__device__ unsigned int g_edge_max_bits;
__device__ unsigned int g_edge_min_bits;

/* ---------------- helpers ----------------------------------------------- */
__device__ __forceinline__ unsigned int encf(float f) {
    unsigned int u = __float_as_uint(f);
    return (u & 0x80000000u) ? ~u : (u | 0x80000000u);
}
__device__ __forceinline__ float decf(unsigned int u) {
    unsigned int b = (u & 0x80000000u) ? (u ^ 0x80000000u) : ~u;
    return __uint_as_float(b);
}
/* pack two floats as bf16x2 (first arg -> low half = lower k index) */
__device__ __forceinline__ uint32_t pack_bf2(float a, float b) {
    __nv_bfloat162 h = __floats2bfloat162_rn(a, b);
    return *(uint32_t*)&h;
}
/* m16n8k16 bf16 MMA: D += A x B (fp32 accum) */
__device__ __forceinline__ void mma_bf16(float* c, uint32_t a0, uint32_t a1,
                                         uint32_t a2, uint32_t a3,
                                         uint32_t b0, uint32_t b1) {
    asm volatile(
        "mma.sync.aligned.m16n8k16.row.col.f32.bf16.bf16.f32 "
        "{%0,%1,%2,%3}, {%4,%5,%6,%7}, {%8,%9}, {%0,%1,%2,%3};"
        : "+f"(c[0]), "+f"(c[1]), "+f"(c[2]), "+f"(c[3])
        : "r"(a0), "r"(a1), "r"(a2), "r"(a3), "r"(b0), "r"(b1));
}

__global__ void init_kernel() {
    g_dist_max_bits = encf(-INFINITY);
    g_edge_max_bits = encf(-INFINITY);
    g_edge_min_bits = encf(INFINITY);
}

/* no-op: shifts launch-index alignment so ncu (-s 5 -c 1) captures main. */
__global__ void align_kernel() {}

/* ============================ main kernel ===============================
 * Grid (64, 32): tile 128 rows x 64 cols, 256 threads (8 warps), 3 CTA/SM.
 * Warp w owns rows [16w, 16w+16); nb = 0..7 column blocks of 8.
 * Operands bf16 in smem (single K=128 phase), MMA m16n8k16: per warp-k16
 * 20 LDS.32 + 8 MMA — half the tf32-k8 version in instrs AND L1 bytes.
 * Word j of a row holds consecutive elements (2j, 2j+1): thread t's MMA
 * fragment regs (k=2t,2t+1) and (k+8) are words base+t and base+t+4.
 * mink = (xs-dot, bf16 -> fp32 acc) - x0_i*x0_j (exact fp32 fixup; k=0
 * zeroed in MMA operands). Also copies x -> out_x in the prologue.
 * ======================================================================== */
__global__ void __launch_bounds__(256, 3)
main_kernel(const float* __restrict__ x,
            const int*   __restrict__ adj,
            float*       __restrict__ dist_out,
            float*       __restrict__ out_x)
{
    extern __shared__ float smf[];
    uint32_t* Aw  = (uint32_t*)smf;                    /* [row][68 words] */
    uint32_t* Bw  = Aw + TM * PW;                      /* [col][68 words] */
    float* x0a  = (float*)(Bw + TN * PW);                      /* [128] */
    float* x0b  = x0a + TM;                                    /* [64]  */
    float* sred = x0b + TN;                                    /* [24]  */

    const int tid  = threadIdx.x;
    const int w    = tid >> 5;
    const int lane = tid & 31;
    const int g    = lane >> 2;            /* 0..7 */
    const int t    = lane & 3;             /* 0..3 */
    const int row0 = blockIdx.y * TM;
    const int col0 = blockIdx.x * TN;
    const int cb   = blockIdx.x;

    /* fused x -> out_x copy (2048 CTAs x 64 float4 = NN*DD) */
    {
        int cta = blockIdx.y * gridDim.x + blockIdx.x;
        if (tid < 64)
            ((float4*)out_x)[cta * 64 + tid] = ((const float4*)x)[cta * 64 + tid];
    }

    /* x0 side arrays */
    if (tid < TM)              x0a[tid]       = x[(size_t)(row0 + tid) * DD];
    else if (tid < TM + TN)    x0b[tid - TM]  = x[(size_t)(col0 + tid - TM) * DD];

    /* ---- A panel: 128 rows x 128 k -> bf16 (one phase) ----
     * thread (row, group G of 8 elems): 2 LDG.128 + 1 STS.128 at word
     * 4G; quarter-warp banks {0,4,...,28}: conflict-free.            */
    for (int idx = tid; idx < TM * 16; idx += 256) {
        int row = idx >> 4, G = idx & 15;
        const float* src = x + (size_t)(row0 + row) * DD + 8 * G;
        float4 v1 = *(const float4*)src;
        float4 v2 = *(const float4*)(src + 4);
        if (G == 0) v1.x = 0.f;                 /* drop x0 from the dot */
        uint4 p;
        p.x = pack_bf2(v1.x, v1.y); p.y = pack_bf2(v1.z, v1.w);
        p.z = pack_bf2(v2.x, v2.y); p.w = pack_bf2(v2.z, v2.w);
        *(uint4*)(Aw + row * PW + 4 * G) = p;
    }
    /* ---- B panel: 64 cols x 128 k -> bf16 ---- */
    for (int idx = tid; idx < TN * 16; idx += 256) {
        int row = idx >> 4, G = idx & 15;
        const float* src = x + (size_t)(col0 + row) * DD + 8 * G;
        float4 v1 = *(const float4*)src;
        float4 v2 = *(const float4*)(src + 4);
        if (G == 0) v1.x = 0.f;
        uint4 p;
        p.x = pack_bf2(v1.x, v1.y); p.y = pack_bf2(v1.z, v1.w);
        p.z = pack_bf2(v2.x, v2.y); p.w = pack_bf2(v2.z, v2.w);
        *(uint4*)(Bw + row * PW + 4 * G) = p;
    }
    __syncthreads();

    float c[8][4];
#pragma unroll
    for (int nb = 0; nb < 8; nb++)
#pragma unroll
        for (int q = 0; q < 4; q++) c[nb][q] = 0.f;

    const int r1l = 16 * w + g;            /* local row of fragment top */

    /* ---- 8 k-steps of m16n8k16 over K=128 ----
     * fragment words: base = row*68 + 8ks; +t (k 2t,2t+1), +t+4 (k+8).
     * banks (4g + 8ks + t) mod 32 distinct per warp: conflict-free.   */
#pragma unroll
    for (int ks = 0; ks < 8; ks++) {
        const int kb = ks * 8 + t;
        uint32_t a0 = Aw[(r1l)     * PW + kb];
        uint32_t a1 = Aw[(r1l + 8) * PW + kb];
        uint32_t a2 = Aw[(r1l)     * PW + kb + 4];
        uint32_t a3 = Aw[(r1l + 8) * PW + kb + 4];
#pragma unroll
        for (int nb = 0; nb < 8; nb++) {
            uint32_t b0 = Bw[(8 * nb + g) * PW + kb];
            uint32_t b1 = Bw[(8 * nb + g) * PW + kb + 4];
            mma_bf16(c[nb], a0, a1, a2, a3, b0, b1);
        }
    }

    /* ---- fused epilogue (identical to R10) ----------------------------- */
    const float x0r1 = x0a[r1l], x0r2 = x0a[r1l + 8];
    const int grow1 = row0 + r1l, grow2 = grow1 + 8;

    float distmax = -INFINITY, edgemax = -INFINITY, edgemin = INFINITY;
    float neg1 = 0.f, S1 = 0.f, m1 = INFINITY; int P1 = 0;
    float neg2 = 0.f, S2 = 0.f, m2 = INFINITY; int P2 = 0;

#pragma unroll
    for (int nb = 0; nb < 8; nb++) {
        const int gcol = col0 + 8 * nb + 2 * t;
        const float x0c0 = x0b[8 * nb + 2 * t], x0c1 = x0b[8 * nb + 2 * t + 1];
        const size_t gb1 = (size_t)grow1 * NN + gcol;
        const size_t gb2 = (size_t)grow2 * NN + gcol;
        const int2 a1v = *(const int2*)(adj + gb1);
        const int2 a2v = *(const int2*)(adj + gb2);

        const float mks[4] = { fmaf(-x0r1, x0c0, c[nb][0]),
                               fmaf(-x0r1, x0c1, c[nb][1]),
                               fmaf(-x0r2, x0c0, c[nb][2]),
                               fmaf(-x0r2, x0c1, c[nb][3]) };
        const int   aas[4] = { a1v.x, a1v.y, a2v.x, a2v.y };

        float dv[4];
#pragma unroll
        for (int q = 0; q < 4; q++) {
            const float mink = mks[q];
            float tm1  = fmaxf(-mink - 1.0f, 1e-7f);
            float srt  = __fsqrt_rn(tm1 * (tm1 + 2.0f));
            float ac   = __logf(1.0f + tm1 + srt);
            float dist = fminf(ac * ac, 50.0f);
            dv[q] = dist;

            distmax = fmaxf(distmax, dist);
            float ei = aas[q] ? mink : 0.0f;
            edgemax = fmaxf(edgemax, ei);
            edgemin = fminf(edgemin, ei);

            float ls   = fmaxf(-dist, LOG_MIN);
            float negc = aas[q] ? 0.0f : fmaxf(__expf(-dist), 1e-15f);
            float Sc   = aas[q] ? ls : 0.0f;
            float mc   = aas[q] ? ls : INFINITY;
            if (q < 2) { neg1 += negc; S1 += Sc; m1 = fminf(m1, mc); P1 += aas[q]; }
            else       { neg2 += negc; S2 += Sc; m2 = fminf(m2, mc); P2 += aas[q]; }
        }
        *(float2*)(dist_out + gb1) = make_float2(dv[0], dv[1]);
        *(float2*)(dist_out + gb2) = make_float2(dv[2], dv[3]);
    }

    /* per-row reduce over the 4 t-lanes (width-4 shfl) */
#pragma unroll
    for (int off = 2; off > 0; off >>= 1) {
        neg1 += __shfl_down_sync(0xffffffffu, neg1, off, 4);
        S1   += __shfl_down_sync(0xffffffffu, S1, off, 4);
        m1    = fminf(m1, __shfl_down_sync(0xffffffffu, m1, off, 4));
        P1   += __shfl_down_sync(0xffffffffu, P1, off, 4);
        neg2 += __shfl_down_sync(0xffffffffu, neg2, off, 4);
        S2   += __shfl_down_sync(0xffffffffu, S2, off, 4);
        m2    = fminf(m2, __shfl_down_sync(0xffffffffu, m2, off, 4));
        P2   += __shfl_down_sync(0xffffffffu, P2, off, 4);
    }
    if (t == 0) {
        g_neg_part[cb][grow1] = neg1; g_S_part[cb][grow1] = S1;
        g_m_part[cb][grow1]   = m1;   g_P_part[cb][grow1] = P1;
        g_neg_part[cb][grow2] = neg2; g_S_part[cb][grow2] = S2;
        g_m_part[cb][grow2]   = m2;   g_P_part[cb][grow2] = P2;
    }

    /* ---- block scalar reductions -> order-independent atomics ---------- */
#pragma unroll
    for (int off = 16; off > 0; off >>= 1) {
        distmax = fmaxf(distmax, __shfl_xor_sync(0xffffffffu, distmax, off));
        edgemax = fmaxf(edgemax, __shfl_xor_sync(0xffffffffu, edgemax, off));
        edgemin = fminf(edgemin, __shfl_xor_sync(0xffffffffu, edgemin, off));
    }
    if (lane == 0) { sred[w] = distmax; sred[8 + w] = edgemax; sred[16 + w] = edgemin; }
    __syncthreads();
    if (tid == 0) {
        float dm = sred[0], em = sred[8], en = sred[16];
        for (int u = 1; u < 8; u++) {
            dm = fmaxf(dm, sred[u]);
            em = fmaxf(em, sred[8 + u]);
            en = fminf(en, sred[16 + u]);
        }
        atomicMax(&g_dist_max_bits, encf(dm));
        atomicMax(&g_edge_max_bits, encf(em));
        atomicMin(&g_edge_min_bits, encf(en));
    }
}

/* ---- per-row loss: 8 warps split the 64 partials (fixed-order combine) - */
__global__ void finalize_rows(const float* __restrict__ dist,
                              const int*   __restrict__ adj)
{
    __shared__ float s_ns[8][32], s_S[8][32], s_m[8][32];
    __shared__ int   s_P[8][32];

    const int lane = threadIdx.x & 31;
    const int w    = threadIdx.x >> 5;
    const int row  = blockIdx.x * 32 + lane;

    float ns = 0.f, S = 0.f, m = INFINITY;
    int P = 0;
#pragma unroll
    for (int cc = 0; cc < 8; cc++) {
        int c = 8 * w + cc;
        ns += g_neg_part[c][row];
        S  += g_S_part[c][row];
        P  += g_P_part[c][row];
        m   = fminf(m, g_m_part[c][row]);
    }
    s_ns[w][lane] = ns; s_S[w][lane] = S; s_m[w][lane] = m; s_P[w][lane] = P;
    __syncthreads();

    if (w == 0) {
        ns = s_ns[0][lane]; S = s_S[0][lane]; m = s_m[0][lane]; P = s_P[0][lane];
#pragma unroll
        for (int u = 1; u < 8; u++) {          /* fixed order */
            ns += s_ns[u][lane];
            S  += s_S[u][lane];
            m   = fminf(m, s_m[u][lane]);
            P  += s_P[u][lane];
        }
        float loss;
        if (P == 0) {
            loss = 0.0f;
        } else {
            float logns = logf(ns);
            if (m - logns >= LOG_MIN + 1e-3f) {
                loss = (float)P * logns - S;
            } else {
                /* exact (rare) fallback matching reference clamps */
                float accf = 0.f;
                for (int j = 0; j < NN; j++) {
                    if (adj[(size_t)row * NN + j]) {
                        float d     = dist[(size_t)row * NN + j];
                        float simi  = fmaxf(expf(-d), 1e-15f);
                        float ratio = fmaxf(simi / ns, 1e-15f);
                        accf += logf(ratio);
                    }
                }
                loss = -accf;
            }
        }
        g_rowloss[row] = loss;
    }
}

__global__ void final_reduce(float* __restrict__ out_scalars) {
    __shared__ float sh[256];
    int tid = threadIdx.x;
    float s = 0.f;
    for (int i = tid; i < NN; i += 256) s += g_rowloss[i];   /* fixed order */
    sh[tid] = s;
    __syncthreads();
    for (int o = 128; o > 0; o >>= 1) {
        if (tid < o) sh[tid] += sh[tid + o];
        __syncthreads();
    }
    if (tid == 0) {
        out_scalars[0] = sh[0];                     /* loss            */
        out_scalars[1] = decf(g_dist_max_bits);     /* max(dist)       */
        out_scalars[2] = decf(g_edge_max_bits);     /* max(edge_inner) */
        out_scalars[3] = decf(g_edge_min_bits);     /* min(edge_inner) */
    }
}

extern "C" void kernel_launch(void* const* d_in, const int* in_sizes, int n_in,
                              void* d_out, int out_size)
{
    const float* x   = (const float*)d_in[0];
    const int*   adj = (const int*)d_in[1];
    float* out      = (float*)d_out;
    float* out_x    = out;
    float* out_dist = out + (size_t)NN * DD;
    float* out_scal = out + (size_t)NN * DD + (size_t)NN * NN;

    cudaFuncSetAttribute(main_kernel,
                         cudaFuncAttributeMaxDynamicSharedMemorySize,
                         SMEM_BYTES);

    init_kernel<<<1, 1>>>();
    align_kernel<<<1, 32>>>();
    align_kernel<<<1, 32>>>();     /* keeps ncu capture on main_kernel (idx 3) */

    dim3 grid(NCB, NRB);
    main_kernel<<<grid, 256, SMEM_BYTES>>>(x, adj, out_dist, out_x);

    finalize_rows<<<NN / 32, 256>>>(out_dist, adj);
    final_reduce<<<1, 256>>>(out_scal);
}